// round 7
// baseline (speedup 1.0000x reference)
#include <cuda_runtime.h>

#define NN 100000
#define NE 1600000
#define NF 128
#define NH 64
#define NC 16

// Scratch (no allocations allowed anywhere). All atomics and all vector
// accesses target these device-DRAM globals only.
__device__ float g_h1[(size_t)NN * NH];    // x @ W1
__device__ float g_agg1[(size_t)NN * NH];  // aggregated layer-1
__device__ float g_h2[(size_t)NN * NC];    // agg1 @ W2
__device__ float g_out[(size_t)NN * NC];   // aggregated layer-2 (pre-softmax)
__device__ float g_deg[NN];
__device__ float g_dinv[NN];

// ---------------------------------------------------------------------------
// Zero agg1, out-scratch, deg
// ---------------------------------------------------------------------------
__global__ void zero_kernel() {
    int stride = gridDim.x * blockDim.x;
    int i0 = blockIdx.x * blockDim.x + threadIdx.x;
    for (int i = i0; i < NN * NH; i += stride) g_agg1[i] = 0.0f;
    for (int i = i0; i < NN * NC; i += stride) g_out[i] = 0.0f;
    for (int i = i0; i < NN; i += stride) g_deg[i] = 0.0f;
}

// ---------------------------------------------------------------------------
// Degree histogram on target nodes + d^{-1/2}
// edge_index is int32: row = ei[e], col = ei[NE + e]
// ---------------------------------------------------------------------------
__global__ void deg_kernel(const int* __restrict__ ei) {
    int stride = gridDim.x * blockDim.x;
    for (int e = blockIdx.x * blockDim.x + threadIdx.x; e < NE; e += stride) {
        int col = ei[NE + e];
        atomicAdd(&g_deg[col], 1.0f);
    }
}

__global__ void dinv_kernel() {
    int i = blockIdx.x * blockDim.x + threadIdx.x;
    if (i < NN) {
        float d = g_deg[i];
        g_dinv[i] = (d > 0.0f) ? rsqrtf(d) : 0.0f;
    }
}

// ---------------------------------------------------------------------------
// GEMM1: h1[N,64] = x[N,128] @ W1[128,64]
// Block tile: 256 rows x 64 cols, 256 threads, each thread 4 rows x 16 cols.
// ---------------------------------------------------------------------------
__global__ __launch_bounds__(256) void gemm1_kernel(const float* __restrict__ x,
                                                    const float* __restrict__ W1) {
    __shared__ float sW[NF * NH];     // 32 KB, whole W1
    __shared__ float sx[256 * 9];     // 256 rows x 8 k, padded stride 9

    int tid = threadIdx.x;
    int r0 = blockIdx.x * 256;

    for (int i = tid; i < NF * NH; i += 256) sW[i] = W1[i];

    int cg = tid & 3;        // col group: cols [cg*16, cg*16+16)
    int rs = tid >> 2;       // row slot: rows r0 + rs + {0,64,128,192}

    float acc[4][16];
#pragma unroll
    for (int j = 0; j < 4; j++)
#pragma unroll
        for (int c = 0; c < 16; c++) acc[j][c] = 0.0f;

    for (int kc = 0; kc < NF; kc += 8) {
        __syncthreads();
#pragma unroll
        for (int i = 0; i < 8; i++) {
            int lin = i * 256 + tid;        // 0..2047 over (row, k)
            int r = lin >> 3;
            int k = lin & 7;
            int gr = r0 + r;
            sx[r * 9 + k] = (gr < NN) ? x[(size_t)gr * NF + kc + k] : 0.0f;
        }
        __syncthreads();
#pragma unroll
        for (int k = 0; k < 8; k++) {
            float xv[4];
#pragma unroll
            for (int j = 0; j < 4; j++) xv[j] = sx[(rs + j * 64) * 9 + k];
            const float* wp = &sW[(kc + k) * NH + cg * 16];
#pragma unroll
            for (int c = 0; c < 16; c++) {
                float w = wp[c];
#pragma unroll
                for (int j = 0; j < 4; j++) acc[j][c] += xv[j] * w;
            }
        }
    }

#pragma unroll
    for (int j = 0; j < 4; j++) {
        int r = r0 + rs + j * 64;
        if (r < NN) {
            float4* op = (float4*)&g_h1[(size_t)r * NH + cg * 16];
#pragma unroll
            for (int q = 0; q < 4; q++)
                op[q] = make_float4(acc[j][q * 4 + 0], acc[j][q * 4 + 1],
                                    acc[j][q * 4 + 2], acc[j][q * 4 + 3]);
        }
    }
}

// ---------------------------------------------------------------------------
// Scatter 1: agg1[col] += h1[row] * norm
// 32 threads/edge, grid-stride; float2 loads/atomics on our globals.
// ---------------------------------------------------------------------------
__global__ void scatter1_kernel(const int* __restrict__ ei) {
    const int total = NE * 32;          // 51.2M, fits int
    int stride = gridDim.x * blockDim.x;
    for (int idx = blockIdx.x * blockDim.x + threadIdx.x; idx < total; idx += stride) {
        int e = idx >> 5;
        int lane = idx & 31;
        int row = ei[e];
        int col = ei[NE + e];
        float norm = g_dinv[row] * g_dinv[col];
        float2 v = ((const float2*)&g_h1[(size_t)row * NH])[lane];
        float* dst = &g_agg1[(size_t)col * NH + lane * 2];
        atomicAdd(dst + 0, v.x * norm);
        atomicAdd(dst + 1, v.y * norm);
    }
}

// ---------------------------------------------------------------------------
// GEMM2: h2[N,16] = agg1[N,64] @ W2[64,16]  (one thread per row)
// ---------------------------------------------------------------------------
__global__ __launch_bounds__(256) void gemm2_kernel(const float* __restrict__ W2) {
    __shared__ float sW[NH * NC];   // 4 KB
    int tid = threadIdx.x;
    for (int i = tid; i < NH * NC; i += 256) sW[i] = W2[i];
    __syncthreads();

    int r = blockIdx.x * 256 + tid;
    if (r >= NN) return;

    float acc[16];
#pragma unroll
    for (int c = 0; c < 16; c++) acc[c] = 0.0f;

    const float4* xp = (const float4*)&g_agg1[(size_t)r * NH];
#pragma unroll
    for (int k4 = 0; k4 < 16; k4++) {
        float4 xv = xp[k4];
        float xs[4] = {xv.x, xv.y, xv.z, xv.w};
#pragma unroll
        for (int t = 0; t < 4; t++) {
            int k = k4 * 4 + t;
            const float* wp = &sW[k * NC];
#pragma unroll
            for (int c = 0; c < 16; c++) acc[c] += xs[t] * wp[c];
        }
    }

    float4* op = (float4*)&g_h2[(size_t)r * NC];
#pragma unroll
    for (int q = 0; q < 4; q++)
        op[q] = make_float4(acc[q * 4 + 0], acc[q * 4 + 1], acc[q * 4 + 2], acc[q * 4 + 3]);
}

// ---------------------------------------------------------------------------
// Scatter 2: g_out[col] += h2[row] * norm   (device scratch only)
// 8 threads/edge, grid-stride.
// ---------------------------------------------------------------------------
__global__ void scatter2_kernel(const int* __restrict__ ei) {
    const int total = NE * 8;           // 12.8M
    int stride = gridDim.x * blockDim.x;
    for (int idx = blockIdx.x * blockDim.x + threadIdx.x; idx < total; idx += stride) {
        int e = idx >> 3;
        int lane = idx & 7;
        int row = ei[e];
        int col = ei[NE + e];
        float norm = g_dinv[row] * g_dinv[col];
        float2 v = ((const float2*)&g_h2[(size_t)row * NC])[lane];
        float* dst = &g_out[(size_t)col * NC + lane * 2];
        atomicAdd(dst + 0, v.x * norm);
        atomicAdd(dst + 1, v.y * norm);
    }
}

// ---------------------------------------------------------------------------
// log_softmax over 16 classes: read g_out scratch, scalar stores to d_out
// ---------------------------------------------------------------------------
__global__ void logsoftmax_kernel(float* __restrict__ out) {
    int r = blockIdx.x * blockDim.x + threadIdx.x;
    if (r >= NN) return;
    const float4* p = (const float4*)&g_out[(size_t)r * NC];
    float4 a0 = p[0], a1 = p[1], a2 = p[2], a3 = p[3];
    float v[16] = {a0.x, a0.y, a0.z, a0.w, a1.x, a1.y, a1.z, a1.w,
                   a2.x, a2.y, a2.z, a2.w, a3.x, a3.y, a3.z, a3.w};
    float m = v[0];
#pragma unroll
    for (int i = 1; i < 16; i++) m = fmaxf(m, v[i]);
    float s = 0.0f;
#pragma unroll
    for (int i = 0; i < 16; i++) s += expf(v[i] - m);
    float ls = m + logf(s);
    float* q = &out[(size_t)r * NC];
#pragma unroll
    for (int i = 0; i < 16; i++) q[i] = v[i] - ls;
}

// ---------------------------------------------------------------------------
extern "C" void kernel_launch(void* const* d_in, const int* in_sizes, int n_in,
                              void* d_out, int out_size) {
    const float* x = (const float*)d_in[0];
    const int* ei = (const int*)d_in[1];
    const float* W1 = (const float*)d_in[2];
    const float* W2 = (const float*)d_in[3];
    float* out = (float*)d_out;

    zero_kernel<<<8192, 256>>>();
    gemm1_kernel<<<(NN + 255) / 256, 256>>>(x, W1);
    deg_kernel<<<4096, 256>>>(ei);
    dinv_kernel<<<(NN + 255) / 256, 256>>>();
    scatter1_kernel<<<16384, 256>>>(ei);
    gemm2_kernel<<<(NN + 255) / 256, 256>>>(W2);
    scatter2_kernel<<<8192, 256>>>(ei);
    logsoftmax_kernel<<<(NN + 255) / 256, 256>>>(out);
}

// round 8
// speedup vs baseline: 2.1894x; 2.1894x over previous
#include <cuda_runtime.h>

#define NN 100000
#define NE 1600000
#define NF 128
#define NH 64
#define NC 16
#define NBLK 391           // ceil(NN/256)

// Scratch (__device__ globals only; no allocations anywhere)
__device__ float g_h1[(size_t)NN * NH];    // (x @ W1) * dinv[row]
__device__ float g_agg1[(size_t)NN * NH];  // layer-1 aggregate
__device__ float g_h2[(size_t)NN * NC];    // (agg1 @ W2) * dinv[row]
__device__ float g_dinv[NN];
__device__ int   g_cnt[NN];                // in-degree (by target col)
__device__ int   g_rowptr[NN];             // exclusive prefix of g_cnt
__device__ int   g_fill[NN];               // fill cursors
__device__ int   g_srcv[NE];               // CSR: source node per slot
__device__ int   g_bsum[NBLK];             // scan block sums
__device__ int   g_boff[NBLK];             // scan block offsets

// ---------------------------------------------------------------------------
__global__ void zero_kernel() {
    int i = blockIdx.x * blockDim.x + threadIdx.x;
    if (i < NN) { g_cnt[i] = 0; g_fill[i] = 0; }
}

// Degree histogram on target nodes (int atomics)
__global__ void deg_kernel(const int* __restrict__ ei) {
    int e = blockIdx.x * blockDim.x + threadIdx.x;
    if (e < NE) atomicAdd(&g_cnt[ei[NE + e]], 1);
}

// ---- 3-pass exclusive scan of g_cnt -> g_rowptr --------------------------
__global__ void scan1_kernel() {
    __shared__ int s[256];
    int tid = threadIdx.x;
    int gid = blockIdx.x * 256 + tid;
    int v = (gid < NN) ? g_cnt[gid] : 0;
    s[tid] = v;
    __syncthreads();
#pragma unroll
    for (int off = 1; off < 256; off <<= 1) {
        int t = (tid >= off) ? s[tid - off] : 0;
        __syncthreads();
        s[tid] += t;
        __syncthreads();
    }
    if (gid < NN) g_rowptr[gid] = s[tid] - v;   // exclusive within block
    if (tid == 255) g_bsum[blockIdx.x] = s[255];
}

__global__ void scan2_kernel() {
    __shared__ int s[512];
    int tid = threadIdx.x;
    int v = (tid < NBLK) ? g_bsum[tid] : 0;
    s[tid] = v;
    __syncthreads();
#pragma unroll
    for (int off = 1; off < 512; off <<= 1) {
        int t = (tid >= off) ? s[tid - off] : 0;
        __syncthreads();
        s[tid] += t;
        __syncthreads();
    }
    if (tid < NBLK) g_boff[tid] = s[tid] - v;   // exclusive block offsets
}

__global__ void scan3_dinv_kernel() {
    int gid = blockIdx.x * 256 + threadIdx.x;
    if (gid < NN) {
        g_rowptr[gid] += g_boff[blockIdx.x];
        int d = g_cnt[gid];
        g_dinv[gid] = (d > 0) ? rsqrtf((float)d) : 0.0f;
    }
}

// CSR fill: slot assignment via atomic cursor
__global__ void fill_kernel(const int* __restrict__ ei) {
    int e = blockIdx.x * blockDim.x + threadIdx.x;
    if (e < NE) {
        int row = ei[e];
        int col = ei[NE + e];
        int pos = atomicAdd(&g_fill[col], 1);
        g_srcv[g_rowptr[col] + pos] = row;
    }
}

// ---------------------------------------------------------------------------
// GEMM1: h1[N,64] = (x[N,128] @ W1[128,64]) * dinv[row]
// Block tile: 256 rows x 64 cols, 256 threads, each thread 4 rows x 16 cols.
// ---------------------------------------------------------------------------
__global__ __launch_bounds__(256) void gemm1_kernel(const float* __restrict__ x,
                                                    const float* __restrict__ W1) {
    __shared__ float sW[NF * NH];     // 32 KB
    __shared__ float sx[256 * 9];     // 256 rows x 8 k, padded

    int tid = threadIdx.x;
    int r0 = blockIdx.x * 256;

    for (int i = tid; i < NF * NH; i += 256) sW[i] = W1[i];

    int cg = tid & 3;
    int rs = tid >> 2;

    float acc[4][16];
#pragma unroll
    for (int j = 0; j < 4; j++)
#pragma unroll
        for (int c = 0; c < 16; c++) acc[j][c] = 0.0f;

    for (int kc = 0; kc < NF; kc += 8) {
        __syncthreads();
#pragma unroll
        for (int i = 0; i < 8; i++) {
            int lin = i * 256 + tid;
            int r = lin >> 3;
            int k = lin & 7;
            int gr = r0 + r;
            sx[r * 9 + k] = (gr < NN) ? x[(size_t)gr * NF + kc + k] : 0.0f;
        }
        __syncthreads();
#pragma unroll
        for (int k = 0; k < 8; k++) {
            float xv[4];
#pragma unroll
            for (int j = 0; j < 4; j++) xv[j] = sx[(rs + j * 64) * 9 + k];
            const float* wp = &sW[(kc + k) * NH + cg * 16];
#pragma unroll
            for (int c = 0; c < 16; c++) {
                float w = wp[c];
#pragma unroll
                for (int j = 0; j < 4; j++) acc[j][c] += xv[j] * w;
            }
        }
    }

#pragma unroll
    for (int j = 0; j < 4; j++) {
        int r = r0 + rs + j * 64;
        if (r < NN) {
            float dv = g_dinv[r];
            float4* op = (float4*)&g_h1[(size_t)r * NH + cg * 16];
#pragma unroll
            for (int q = 0; q < 4; q++)
                op[q] = make_float4(acc[j][q * 4 + 0] * dv, acc[j][q * 4 + 1] * dv,
                                    acc[j][q * 4 + 2] * dv, acc[j][q * 4 + 3] * dv);
        }
    }
}

// ---------------------------------------------------------------------------
// Gather 1: agg1[n] = dinv[n] * sum_{src in CSR[n]} h1[src]   (warp per node)
// ---------------------------------------------------------------------------
__global__ __launch_bounds__(256) void gather1_kernel() {
    int w = (blockIdx.x * blockDim.x + threadIdx.x) >> 5;
    int lane = threadIdx.x & 31;
    if (w >= NN) return;
    int start = g_rowptr[w];
    int deg = g_cnt[w];
    float ax = 0.0f, ay = 0.0f;
    int i = 0;
    for (; i + 4 <= deg; i += 4) {
        int s0 = g_srcv[start + i + 0];
        int s1 = g_srcv[start + i + 1];
        int s2 = g_srcv[start + i + 2];
        int s3 = g_srcv[start + i + 3];
        float2 v0 = ((const float2*)&g_h1[(size_t)s0 * NH])[lane];
        float2 v1 = ((const float2*)&g_h1[(size_t)s1 * NH])[lane];
        float2 v2 = ((const float2*)&g_h1[(size_t)s2 * NH])[lane];
        float2 v3 = ((const float2*)&g_h1[(size_t)s3 * NH])[lane];
        ax += v0.x + v1.x + v2.x + v3.x;
        ay += v0.y + v1.y + v2.y + v3.y;
    }
    for (; i < deg; i++) {
        int s0 = g_srcv[start + i];
        float2 v0 = ((const float2*)&g_h1[(size_t)s0 * NH])[lane];
        ax += v0.x; ay += v0.y;
    }
    float dc = g_dinv[w];
    ((float2*)&g_agg1[(size_t)w * NH])[lane] = make_float2(ax * dc, ay * dc);
}

// ---------------------------------------------------------------------------
// GEMM2: h2[N,16] = (agg1[N,64] @ W2[64,16]) * dinv[row]
// ---------------------------------------------------------------------------
__global__ __launch_bounds__(256) void gemm2_kernel(const float* __restrict__ W2) {
    __shared__ float sW[NH * NC];
    int tid = threadIdx.x;
    for (int i = tid; i < NH * NC; i += 256) sW[i] = W2[i];
    __syncthreads();

    int r = blockIdx.x * 256 + tid;
    if (r >= NN) return;

    float acc[16];
#pragma unroll
    for (int c = 0; c < 16; c++) acc[c] = 0.0f;

    const float4* xp = (const float4*)&g_agg1[(size_t)r * NH];
#pragma unroll
    for (int k4 = 0; k4 < 16; k4++) {
        float4 xv = xp[k4];
        float xs[4] = {xv.x, xv.y, xv.z, xv.w};
#pragma unroll
        for (int t = 0; t < 4; t++) {
            const float* wp = &sW[(k4 * 4 + t) * NC];
#pragma unroll
            for (int c = 0; c < 16; c++) acc[c] += xs[t] * wp[c];
        }
    }

    float dv = g_dinv[r];
    float4* op = (float4*)&g_h2[(size_t)r * NC];
#pragma unroll
    for (int q = 0; q < 4; q++)
        op[q] = make_float4(acc[q * 4 + 0] * dv, acc[q * 4 + 1] * dv,
                            acc[q * 4 + 2] * dv, acc[q * 4 + 3] * dv);
}

// ---------------------------------------------------------------------------
// Gather 2 + log_softmax fused: 2 nodes per warp (16 lanes each).
// out[n, l] = logsoftmax( dinv[n] * sum h2[src, l] )
// ---------------------------------------------------------------------------
__global__ __launch_bounds__(256) void gather2_softmax_kernel(float* __restrict__ out) {
    int w = (blockIdx.x * blockDim.x + threadIdx.x) >> 5;
    int lane = threadIdx.x & 31;
    int node = w * 2 + (lane >> 4);
    int l = lane & 15;
    if (node >= NN) return;

    int start = g_rowptr[node];
    int deg = g_cnt[node];
    float acc = 0.0f;
    int i = 0;
    for (; i + 4 <= deg; i += 4) {
        int s0 = g_srcv[start + i + 0];
        int s1 = g_srcv[start + i + 1];
        int s2 = g_srcv[start + i + 2];
        int s3 = g_srcv[start + i + 3];
        acc += g_h2[(size_t)s0 * NC + l] + g_h2[(size_t)s1 * NC + l]
             + g_h2[(size_t)s2 * NC + l] + g_h2[(size_t)s3 * NC + l];
    }
    for (; i < deg; i++) acc += g_h2[(size_t)g_srcv[start + i] * NC + l];
    acc *= g_dinv[node];

    // log_softmax across the 16-lane group
    float m = acc;
#pragma unroll
    for (int off = 8; off > 0; off >>= 1)
        m = fmaxf(m, __shfl_xor_sync(0xffffffffu, m, off, 16));
    float ex = expf(acc - m);
    float s = ex;
#pragma unroll
    for (int off = 8; off > 0; off >>= 1)
        s += __shfl_xor_sync(0xffffffffu, s, off, 16);
    out[(size_t)node * NC + l] = (acc - m) - logf(s);
}

// ---------------------------------------------------------------------------
extern "C" void kernel_launch(void* const* d_in, const int* in_sizes, int n_in,
                              void* d_out, int out_size) {
    const float* x = (const float*)d_in[0];
    const int* ei = (const int*)d_in[1];
    const float* W1 = (const float*)d_in[2];
    const float* W2 = (const float*)d_in[3];
    float* out = (float*)d_out;

    zero_kernel<<<NBLK, 256>>>();
    deg_kernel<<<(NE + 255) / 256, 256>>>(ei);
    scan1_kernel<<<NBLK, 256>>>();
    scan2_kernel<<<1, 512>>>();
    scan3_dinv_kernel<<<NBLK, 256>>>();
    gemm1_kernel<<<NBLK, 256>>>(x, W1);             // needs dinv (epilogue scale)
    fill_kernel<<<(NE + 255) / 256, 256>>>(ei);
    gather1_kernel<<<(NN * 32 + 255) / 256, 256>>>();
    gemm2_kernel<<<NBLK, 256>>>(W2);
    gather2_softmax_kernel<<<((NN + 1) / 2 * 32 + 255) / 256, 256>>>(out);
}

// round 9
// speedup vs baseline: 2.4893x; 1.1369x over previous
#include <cuda_runtime.h>

#define NN 100000
#define NE 1600000
#define NF 128
#define NH 64
#define NC 16
#define NBLK 391           // ceil(NN/256) gemm1 tiles
#define G1A 196            // gemm1 tiles in fat kernel A
#define G1B (NBLK - G1A)   // gemm1 tiles in fat kernel B
#define EDGE_BLKS 1024     // grid-stride blocks for deg/fill parts

// Scratch (__device__ globals only)
__device__ float g_h1[(size_t)NN * NH];    // x @ W1   (unscaled)
__device__ float g_agg1[(size_t)NN * NH];  // layer-1 aggregate (normalized)
__device__ float g_h2[(size_t)NN * NC];    // (agg1 @ W2) * dinv[row]
__device__ float g_dinv[NN];
__device__ int   g_cnt[NN];
__device__ int   g_rowptr[NN];
__device__ int   g_fill[NN];
__device__ int   g_srcv[NE];
__device__ int   g_bsum[NBLK];
__device__ int   g_boff[NBLK];

// ---------------------------------------------------------------------------
__global__ void zero_kernel() {
    int i = blockIdx.x * blockDim.x + threadIdx.x;
    if (i < NN) { g_cnt[i] = 0; g_fill[i] = 0; }
}

// ---------------------------------------------------------------------------
// GEMM1 tile body (256 rows x 64 cols per block), no dinv scaling.
// ---------------------------------------------------------------------------
__device__ __forceinline__ void gemm1_tile(int b, const float* __restrict__ x,
                                           const float* __restrict__ W1,
                                           float* sW, float* sx) {
    int tid = threadIdx.x;
    int r0 = b * 256;

    for (int i = tid; i < NF * NH; i += 256) sW[i] = W1[i];

    int cg = tid & 3;
    int rs = tid >> 2;

    float acc[4][16];
#pragma unroll
    for (int j = 0; j < 4; j++)
#pragma unroll
        for (int c = 0; c < 16; c++) acc[j][c] = 0.0f;

    for (int kc = 0; kc < NF; kc += 8) {
        __syncthreads();
#pragma unroll
        for (int i = 0; i < 8; i++) {
            int lin = i * 256 + tid;
            int r = lin >> 3;
            int k = lin & 7;
            int gr = r0 + r;
            sx[r * 9 + k] = (gr < NN) ? x[(size_t)gr * NF + kc + k] : 0.0f;
        }
        __syncthreads();
#pragma unroll
        for (int k = 0; k < 8; k++) {
            float xv[4];
#pragma unroll
            for (int j = 0; j < 4; j++) xv[j] = sx[(rs + j * 64) * 9 + k];
            const float* wp = &sW[(kc + k) * NH + cg * 16];
#pragma unroll
            for (int c = 0; c < 16; c++) {
                float w = wp[c];
#pragma unroll
                for (int j = 0; j < 4; j++) acc[j][c] += xv[j] * w;
            }
        }
    }

#pragma unroll
    for (int j = 0; j < 4; j++) {
        int r = r0 + rs + j * 64;
        if (r < NN) {
            float4* op = (float4*)&g_h1[(size_t)r * NH + cg * 16];
#pragma unroll
            for (int q = 0; q < 4; q++)
                op[q] = make_float4(acc[j][q * 4 + 0], acc[j][q * 4 + 1],
                                    acc[j][q * 4 + 2], acc[j][q * 4 + 3]);
        }
    }
}

// Fat kernel A: gemm1 tiles [0, G1A) ∥ degree histogram
__global__ __launch_bounds__(256) void fatA_kernel(const float* __restrict__ x,
                                                   const float* __restrict__ W1,
                                                   const int* __restrict__ ei) {
    __shared__ float sW[NF * NH];
    __shared__ float sx[256 * 9];
    int b = blockIdx.x;
    if (b < G1A) {
        gemm1_tile(b, x, W1, sW, sx);
    } else {
        int stride = (gridDim.x - G1A) * 256;
        for (int e = (b - G1A) * 256 + threadIdx.x; e < NE; e += stride)
            atomicAdd(&g_cnt[ei[NE + e]], 1);
    }
}

// Fat kernel B: gemm1 tiles [G1A, NBLK) ∥ CSR fill
__global__ __launch_bounds__(256) void fatB_kernel(const float* __restrict__ x,
                                                   const float* __restrict__ W1,
                                                   const int* __restrict__ ei) {
    __shared__ float sW[NF * NH];
    __shared__ float sx[256 * 9];
    int b = blockIdx.x;
    if (b < G1B) {
        gemm1_tile(b + G1A, x, W1, sW, sx);
    } else {
        int stride = (gridDim.x - G1B) * 256;
        for (int e = (b - G1B) * 256 + threadIdx.x; e < NE; e += stride) {
            int row = ei[e];
            int col = ei[NE + e];
            int pos = atomicAdd(&g_fill[col], 1);
            g_srcv[g_rowptr[col] + pos] = row;
        }
    }
}

// ---- 3-pass exclusive scan of g_cnt -> g_rowptr + dinv --------------------
__global__ void scan1_kernel() {
    __shared__ int s[256];
    int tid = threadIdx.x;
    int gid = blockIdx.x * 256 + tid;
    int v = (gid < NN) ? g_cnt[gid] : 0;
    s[tid] = v;
    __syncthreads();
#pragma unroll
    for (int off = 1; off < 256; off <<= 1) {
        int t = (tid >= off) ? s[tid - off] : 0;
        __syncthreads();
        s[tid] += t;
        __syncthreads();
    }
    if (gid < NN) g_rowptr[gid] = s[tid] - v;
    if (tid == 255) g_bsum[blockIdx.x] = s[255];
}

__global__ void scan2_kernel() {
    __shared__ int s[512];
    int tid = threadIdx.x;
    int v = (tid < NBLK) ? g_bsum[tid] : 0;
    s[tid] = v;
    __syncthreads();
#pragma unroll
    for (int off = 1; off < 512; off <<= 1) {
        int t = (tid >= off) ? s[tid - off] : 0;
        __syncthreads();
        s[tid] += t;
        __syncthreads();
    }
    if (tid < NBLK) g_boff[tid] = s[tid] - v;
}

__global__ void scan3_dinv_kernel() {
    int gid = blockIdx.x * 256 + threadIdx.x;
    if (gid < NN) {
        g_rowptr[gid] += g_boff[blockIdx.x];
        int d = g_cnt[gid];
        g_dinv[gid] = (d > 0) ? rsqrtf((float)d) : 0.0f;
    }
}

// ---------------------------------------------------------------------------
// Gather 1: agg1[n] = dinv[n] * sum dinv[s] * h1[s]   (warp per node)
// ---------------------------------------------------------------------------
__global__ __launch_bounds__(256) void gather1_kernel() {
    int w = (blockIdx.x * blockDim.x + threadIdx.x) >> 5;
    int lane = threadIdx.x & 31;
    if (w >= NN) return;
    int start = g_rowptr[w];
    int deg = g_cnt[w];
    float ax = 0.0f, ay = 0.0f;
    int i = 0;
    for (; i + 4 <= deg; i += 4) {
        int s0 = g_srcv[start + i + 0];
        int s1 = g_srcv[start + i + 1];
        int s2 = g_srcv[start + i + 2];
        int s3 = g_srcv[start + i + 3];
        float d0 = g_dinv[s0], d1 = g_dinv[s1], d2 = g_dinv[s2], d3 = g_dinv[s3];
        float2 v0 = ((const float2*)&g_h1[(size_t)s0 * NH])[lane];
        float2 v1 = ((const float2*)&g_h1[(size_t)s1 * NH])[lane];
        float2 v2 = ((const float2*)&g_h1[(size_t)s2 * NH])[lane];
        float2 v3 = ((const float2*)&g_h1[(size_t)s3 * NH])[lane];
        ax += v0.x * d0 + v1.x * d1 + v2.x * d2 + v3.x * d3;
        ay += v0.y * d0 + v1.y * d1 + v2.y * d2 + v3.y * d3;
    }
    for (; i < deg; i++) {
        int s0 = g_srcv[start + i];
        float d0 = g_dinv[s0];
        float2 v0 = ((const float2*)&g_h1[(size_t)s0 * NH])[lane];
        ax += v0.x * d0; ay += v0.y * d0;
    }
    float dc = g_dinv[w];
    ((float2*)&g_agg1[(size_t)w * NH])[lane] = make_float2(ax * dc, ay * dc);
}

// ---------------------------------------------------------------------------
// GEMM2: h2[N,16] = (agg1[N,64] @ W2[64,16]) * dinv[row]
// ---------------------------------------------------------------------------
__global__ __launch_bounds__(256) void gemm2_kernel(const float* __restrict__ W2) {
    __shared__ float sW[NH * NC];
    int tid = threadIdx.x;
    for (int i = tid; i < NH * NC; i += 256) sW[i] = W2[i];
    __syncthreads();

    int r = blockIdx.x * 256 + tid;
    if (r >= NN) return;

    float acc[16];
#pragma unroll
    for (int c = 0; c < 16; c++) acc[c] = 0.0f;

    const float4* xp = (const float4*)&g_agg1[(size_t)r * NH];
#pragma unroll
    for (int k4 = 0; k4 < 16; k4++) {
        float4 xv = xp[k4];
        float xs[4] = {xv.x, xv.y, xv.z, xv.w};
#pragma unroll
        for (int t = 0; t < 4; t++) {
            const float* wp = &sW[(k4 * 4 + t) * NC];
#pragma unroll
            for (int c = 0; c < 16; c++) acc[c] += xs[t] * wp[c];
        }
    }

    float dv = g_dinv[r];
    float4* op = (float4*)&g_h2[(size_t)r * NC];
#pragma unroll
    for (int q = 0; q < 4; q++)
        op[q] = make_float4(acc[q * 4 + 0] * dv, acc[q * 4 + 1] * dv,
                            acc[q * 4 + 2] * dv, acc[q * 4 + 3] * dv);
}

// ---------------------------------------------------------------------------
// Gather 2 + log_softmax fused: 2 nodes per warp (16 lanes each)
// ---------------------------------------------------------------------------
__global__ __launch_bounds__(256) void gather2_softmax_kernel(float* __restrict__ out) {
    int w = (blockIdx.x * blockDim.x + threadIdx.x) >> 5;
    int lane = threadIdx.x & 31;
    int node = w * 2 + (lane >> 4);
    int l = lane & 15;
    if (node >= NN) return;

    int start = g_rowptr[node];
    int deg = g_cnt[node];
    float acc = 0.0f;
    int i = 0;
    for (; i + 4 <= deg; i += 4) {
        int s0 = g_srcv[start + i + 0];
        int s1 = g_srcv[start + i + 1];
        int s2 = g_srcv[start + i + 2];
        int s3 = g_srcv[start + i + 3];
        acc += g_h2[(size_t)s0 * NC + l] + g_h2[(size_t)s1 * NC + l]
             + g_h2[(size_t)s2 * NC + l] + g_h2[(size_t)s3 * NC + l];
    }
    for (; i < deg; i++) acc += g_h2[(size_t)g_srcv[start + i] * NC + l];
    acc *= g_dinv[node];

    float m = acc;
#pragma unroll
    for (int off = 8; off > 0; off >>= 1)
        m = fmaxf(m, __shfl_xor_sync(0xffffffffu, m, off, 16));
    float ex = expf(acc - m);
    float s = ex;
#pragma unroll
    for (int off = 8; off > 0; off >>= 1)
        s += __shfl_xor_sync(0xffffffffu, s, off, 16);
    out[(size_t)node * NC + l] = (acc - m) - logf(s);
}

// ---------------------------------------------------------------------------
extern "C" void kernel_launch(void* const* d_in, const int* in_sizes, int n_in,
                              void* d_out, int out_size) {
    const float* x = (const float*)d_in[0];
    const int* ei = (const int*)d_in[1];
    const float* W1 = (const float*)d_in[2];
    const float* W2 = (const float*)d_in[3];
    float* out = (float*)d_out;

    zero_kernel<<<NBLK, 256>>>();
    fatA_kernel<<<G1A + EDGE_BLKS, 256>>>(x, W1, ei);   // gemm1 A ∥ deg
    scan1_kernel<<<NBLK, 256>>>();
    scan2_kernel<<<1, 512>>>();
    scan3_dinv_kernel<<<NBLK, 256>>>();
    fatB_kernel<<<G1B + EDGE_BLKS, 256>>>(x, W1, ei);   // gemm1 B ∥ fill
    gather1_kernel<<<(NN * 32 + 255) / 256, 256>>>();
    gemm2_kernel<<<NBLK, 256>>>(W2);
    gather2_softmax_kernel<<<((NN + 1) / 2 * 32 + 255) / 256, 256>>>(out);
}